// round 2
// baseline (speedup 1.0000x reference)
#include <cuda_runtime.h>
#include <cuda_bf16.h>
#include <math.h>

// ----------------------------------------------------------------------------
// QSP: u = Rz(phi0) * prod_{k=1..127} [ Wx(theta) * Rz(phi_k) ], output
// (Re u00, Im u00) per theta.
//
// Laurent form: u00(theta) = sum_{j=0..127} alpha_j * w^{2j-127},  w = e^{i theta}.
// Coefficients alpha_j depend only on phis -> computed once by coef_kernel.
// Per-row evaluation: u00 = w^{-127} * Horner_{j}(alpha, z) with z = w^2.
// ----------------------------------------------------------------------------

__device__ float2 g_coef[128];

// ---- Kernel 1: compute Laurent coefficients (1 block, 256 threads) ----------
// State arrays indexed by m = exponent + 127 (0..254), stored at slot m+1 in
// padded [258] arrays so m-1 / m+1 neighbor reads never go out of bounds.
__global__ void coef_kernel(const float* __restrict__ phis)
{
    __shared__ float2 e[128];
    __shared__ float2 Abuf[2][258];
    __shared__ float2 Bbuf[2][258];

    const int t = threadIdx.x;  // 0..255

    if (t < 128) {
        float s, c;
        sincosf(phis[t], &s, &c);
        e[t] = make_float2(c, s);   // e_k = exp(i phi_k)
    }

    // zero both buffers (incl. pads)
    const float2 z2 = make_float2(0.f, 0.f);
    Abuf[0][t + 1] = z2; Abuf[1][t + 1] = z2;
    Bbuf[0][t + 1] = z2; Bbuf[1][t + 1] = z2;
    if (t == 0) {
        Abuf[0][0] = z2; Abuf[0][257] = z2;
        Abuf[1][0] = z2; Abuf[1][257] = z2;
        Bbuf[0][0] = z2; Bbuf[0][257] = z2;
        Bbuf[1][0] = z2; Bbuf[1][257] = z2;
    }
    __syncthreads();

    // init: A = e0 at exponent 0 (m=127 -> slot 128), B = 0
    if (t == 127) Abuf[0][128] = e[0];
    __syncthreads();

    int cur = 0;
    for (int k = 1; k <= 127; ++k) {
        const float2 ek = e[k];
        const int m = t + 1;  // slot for this thread's exponent index

        const float2 Al = Abuf[cur][m - 1];
        const float2 Bl = Bbuf[cur][m - 1];
        const float2 Ar = Abuf[cur][m + 1];
        const float2 Br = Bbuf[cur][m + 1];

        // sum = (A+B) at exponent m-1  (the "* w" contribution)
        const float sr = Al.x + Bl.x, si = Al.y + Bl.y;
        // dif = (A-B) at exponent m+1  (the "* w^-1" contribution)
        const float dr = Ar.x - Br.x, di = Ar.y - Br.y;

        const float ur = 0.5f * (sr + dr), ui = 0.5f * (si + di);  // -> A'
        const float vr = 0.5f * (sr - dr), vi = 0.5f * (si - di);  // -> B'

        // A' = e_k * u ;  B' = conj(e_k) * v
        const int nxt = cur ^ 1;
        Abuf[nxt][m] = make_float2(ur * ek.x - ui * ek.y,
                                   ur * ek.y + ui * ek.x);
        Bbuf[nxt][m] = make_float2(vr * ek.x + vi * ek.y,
                                   vi * ek.x - vr * ek.y);
        cur = nxt;
        __syncthreads();
    }

    // alpha_j lives at exponent 2j-127 -> m = 2j -> slot 2j+1
    if (t < 128) g_coef[t] = Abuf[cur][2 * t + 1];
}

// ---- Kernel 2: per-row Horner evaluation ------------------------------------
__global__ void __launch_bounds__(256)
eval_kernel(const float* __restrict__ th, float* __restrict__ out, int n)
{
    __shared__ float2 sc[128];
    if (threadIdx.x < 128) sc[threadIdx.x] = g_coef[threadIdx.x];
    __syncthreads();

    const int i = blockIdx.x * blockDim.x + threadIdx.x;
    if (i >= n) return;

    const float t = th[i];

    float s2, c2;  sincosf(2.0f * t, &s2, &c2);      // z = w^2
    float sp, cp;  sincosf(127.0f * t, &sp, &cp);    // w^127 phase

    float ar = sc[127].x;
    float ai = sc[127].y;

#pragma unroll 18
    for (int j = 126; j >= 0; --j) {
        const float2 C = sc[j];
        const float nr = fmaf(-ai, s2, fmaf(ar, c2, C.x));
        const float ni = fmaf( ai, c2, fmaf(ar, s2, C.y));
        ar = nr;
        ai = ni;
    }

    // multiply by w^{-127} = (cp, -sp)
    out[i]     = fmaf(ai, sp,  ar * cp);   // Re
    out[i + n] = fmaf(ai, cp, -ar * sp);   // Im
}

// ---- launch -----------------------------------------------------------------
extern "C" void kernel_launch(void* const* d_in, const int* in_sizes, int n_in,
                              void* d_out, int out_size)
{
    const float* th   = (const float*)d_in[0];
    const float* phis = (const float*)d_in[1];
    float* out = (float*)d_out;
    const int n = in_sizes[0];  // B rows

    coef_kernel<<<1, 256>>>(phis);
    eval_kernel<<<(n + 255) / 256, 256>>>(th, out, n);
}

// round 3
// speedup vs baseline: 1.9129x; 1.9129x over previous
#include <cuda_runtime.h>
#include <cuda_bf16.h>
#include <math.h>

// ----------------------------------------------------------------------------
// QSP: u = Rz(phi0) * prod_{k=1..127} [ Wx(theta) * Rz(phi_k) ]; output
// (Re u00, Im u00) per theta.
//
// Laurent form: u00(theta) = sum_{j=0..127} alpha_j * w^(2j-127),  w = e^{i th}.
// coef_kernel computes alpha_j (depends only on phis).
// eval_kernel: u00 = w^-127 * Horner(alpha, z), z = w^2 — two rows per thread
// packed into fma.rn.f32x2 (FFMA2) lanes.
// ----------------------------------------------------------------------------

__device__ float2 g_coef[128];

// ---- packed f32x2 helpers ---------------------------------------------------
#define FMA2(d, a, b, c) \
    asm("fma.rn.f32x2 %0, %1, %2, %3;" : "=l"(d) : "l"(a), "l"(b), "l"(c))
#define PACK2(d, lo, hi) \
    asm("mov.b64 %0, {%1, %2};" : "=l"(d) : "f"(lo), "f"(hi))
#define UNPACK2(lo, hi, s) \
    asm("mov.b64 {%0, %1}, %2;" : "=f"(lo), "=f"(hi) : "l"(s))

// ---- Kernel 1: compute Laurent coefficients (1 block, 256 threads) ----------
// State indexed by m = exponent + 127 (0..254), stored at slot m+1 in padded
// [258] arrays so m-1 / m+1 neighbor reads never go out of bounds.
__global__ void coef_kernel(const float* __restrict__ phis)
{
    __shared__ float2 e[128];
    __shared__ float2 Abuf[2][258];
    __shared__ float2 Bbuf[2][258];

    const int t = threadIdx.x;  // 0..255

    if (t < 128) {
        float s, c;
        sincosf(phis[t], &s, &c);
        e[t] = make_float2(c, s);   // e_k = exp(i phi_k)
    }

    const float2 z2 = make_float2(0.f, 0.f);
    Abuf[0][t + 1] = z2; Abuf[1][t + 1] = z2;
    Bbuf[0][t + 1] = z2; Bbuf[1][t + 1] = z2;
    if (t == 0) {
        Abuf[0][0] = z2; Abuf[0][257] = z2;
        Abuf[1][0] = z2; Abuf[1][257] = z2;
        Bbuf[0][0] = z2; Bbuf[0][257] = z2;
        Bbuf[1][0] = z2; Bbuf[1][257] = z2;
    }
    __syncthreads();

    if (t == 127) Abuf[0][128] = e[0];  // A = e0 at exponent 0
    __syncthreads();

    int cur = 0;
    for (int k = 1; k <= 127; ++k) {
        const float2 ek = e[k];
        const int m = t + 1;

        const float2 Al = Abuf[cur][m - 1];
        const float2 Bl = Bbuf[cur][m - 1];
        const float2 Ar = Abuf[cur][m + 1];
        const float2 Br = Bbuf[cur][m + 1];

        const float sr = Al.x + Bl.x, si = Al.y + Bl.y;   // (A+B) @ m-1
        const float dr = Ar.x - Br.x, di = Ar.y - Br.y;   // (A-B) @ m+1

        const float ur = 0.5f * (sr + dr), ui = 0.5f * (si + di);
        const float vr = 0.5f * (sr - dr), vi = 0.5f * (si - di);

        const int nxt = cur ^ 1;
        Abuf[nxt][m] = make_float2(ur * ek.x - ui * ek.y,
                                   ur * ek.y + ui * ek.x);   // e_k * u
        Bbuf[nxt][m] = make_float2(vr * ek.x + vi * ek.y,
                                   vi * ek.x - vr * ek.y);   // conj(e_k) * v
        cur = nxt;
        __syncthreads();
    }

    if (t < 128) g_coef[t] = Abuf[cur][2 * t + 1];  // exponent 2j-127 -> slot 2j+1
}

// ---- Kernel 2: per-row Horner evaluation, 2 rows/thread via f32x2 -----------
__global__ void __launch_bounds__(256)
eval_kernel(const float2* __restrict__ th2, float* __restrict__ out, int n)
{
    // coefficients duplicated: sc[j] = (Cx, Cx, Cy, Cy) -> one LDS.128 gives
    // both packed constants in aligned 64-bit register pairs.
    __shared__ float4 sc[128];
    if (threadIdx.x < 128) {
        const float2 c = g_coef[threadIdx.x];
        sc[threadIdx.x] = make_float4(c.x, c.x, c.y, c.y);
    }
    __syncthreads();

    const int np = n >> 1;  // row pairs
    const int i = blockIdx.x * blockDim.x + threadIdx.x;
    if (i >= np) return;

    const float2 tt = th2[i];   // two adjacent thetas

    float s2a, c2a, s2b, c2b;
    sincosf(2.0f * tt.x, &s2a, &c2a);
    sincosf(2.0f * tt.y, &s2b, &c2b);
    float spa, cpa, spb, cpb;
    sincosf(127.0f * tt.x, &spa, &cpa);
    sincosf(127.0f * tt.y, &spb, &cpb);

    unsigned long long c2p, s2p, ns2p;
    PACK2(c2p,  c2a,  c2b);
    PACK2(s2p,  s2a,  s2b);
    PACK2(ns2p, -s2a, -s2b);

    const ulonglong2* scv = reinterpret_cast<const ulonglong2*>(sc);

    ulonglong2 C = scv[127];
    unsigned long long ar = C.x;   // (Cx127, Cx127)
    unsigned long long ai = C.y;   // (Cy127, Cy127)

#pragma unroll 16
    for (int j = 126; j >= 0; --j) {
        C = scv[j];                      // LDS.128 broadcast
        unsigned long long t0, t1;
        FMA2(t0, ai, ns2p, C.x);         // -ai*s2 + Cx
        FMA2(t1, ar, s2p,  C.y);         //  ar*s2 + Cy
        FMA2(ar, ar, c2p,  t0);          //  ar*c2 + t0
        FMA2(ai, ai, c2p,  t1);          //  ai*c2 + t1
    }

    float ar_a, ar_b, ai_a, ai_b;
    UNPACK2(ar_a, ar_b, ar);
    UNPACK2(ai_a, ai_b, ai);

    // multiply by w^-127 = (cos(127t), -sin(127t))
    float2 re, im;
    re.x = fmaf(ai_a, spa,  ar_a * cpa);
    re.y = fmaf(ai_b, spb,  ar_b * cpb);
    im.x = fmaf(ai_a, cpa, -ar_a * spa);
    im.y = fmaf(ai_b, cpb, -ar_b * spb);

    reinterpret_cast<float2*>(out)[i]      = re;   // rows 2i, 2i+1
    reinterpret_cast<float2*>(out + n)[i]  = im;
}

// ---- launch -----------------------------------------------------------------
extern "C" void kernel_launch(void* const* d_in, const int* in_sizes, int n_in,
                              void* d_out, int out_size)
{
    const float* th   = (const float*)d_in[0];
    const float* phis = (const float*)d_in[1];
    float* out = (float*)d_out;
    const int n = in_sizes[0];  // B rows (even)

    coef_kernel<<<1, 256>>>(phis);

    const int np = n >> 1;
    eval_kernel<<<(np + 255) / 256, 256>>>(
        reinterpret_cast<const float2*>(th), out, n);
}